// round 8
// baseline (speedup 1.0000x reference)
#include <cuda_runtime.h>
#include <cuda_bf16.h>
#include <cuda_fp8.h>
#include <math.h>
#include <stdint.h>

// ---------------------------------------------------------------------------
// Problem constants
// ---------------------------------------------------------------------------
namespace {
constexpr int Bb   = 2;
constexpr int Ll   = 512;
constexpr int Vv   = 50304;
constexpr int Dd   = 768;
constexpr int NL   = 2;
constexpr int DI   = 1536;
constexpr int Ns   = 16;
constexpr int DTR  = 48;
constexpr int Hh   = 1536;
constexpr int CND  = 128;
constexpr int FREQ = 256;
constexpr int MASKID = 50257;
constexpr int BL   = Bb * Ll;                 // 1024
constexpr int DTBC = DTR + 2 * Ns;            // 80
constexpr int XZC  = 2 * 2 * DI;              // 6144 combined xz row (2 dirs)

// fp32 scratch pool
constexpr size_t S_H     = (size_t)BL * Dd;
constexpr size_t OFF_H     = 0;
constexpr size_t OFF_C     = OFF_H    + S_H;
constexpr size_t OFF_COND  = OFF_C    + (size_t)Bb * CND;
constexpr size_t OFF_XZC   = OFF_COND + (size_t)Bb * 3 * Dd;
constexpr size_t OFF_DTBC  = OFF_XZC  + (size_t)BL * XZC;
constexpr size_t OFF_DELTA = OFF_DTBC + 2 * (size_t)BL * DTBC;
constexpr size_t OFF_YO    = OFF_DELTA + 2 * (size_t)BL * DI;
constexpr size_t OFF_MLP12 = OFF_YO   + 2 * (size_t)BL * Dd;
constexpr size_t TOTALF    = OFF_MLP12 + (size_t)BL * 2 * Hh;

// fp8 pool (element counts == byte counts)
constexpr size_t HS_TE    = (size_t)Vv * Dd;
constexpr size_t HS_WINT  = (size_t)2 * DI * Dd;
constexpr size_t HS_WXT   = (size_t)DTBC * DI;
constexpr size_t HS_WDTT  = (size_t)DI * DTR;
constexpr size_t HS_WOUTT = (size_t)Dd * DI;
constexpr size_t HS_W12T  = (size_t)Hh * Dd;
constexpr size_t HS_W3T   = (size_t)Dd * Hh;

constexpr size_t HB_TE    = 0;
constexpr size_t HB_WINT  = HB_TE    + HS_TE;
constexpr size_t HB_WXT   = HB_WINT  + 4 * HS_WINT;
constexpr size_t HB_WDTT  = HB_WXT   + 4 * HS_WXT;
constexpr size_t HB_WOUTT = HB_WDTT  + 4 * HS_WDTT;
constexpr size_t HB_W12T  = HB_WOUTT + 4 * HS_WOUTT;   // l0w1,l0w2,l1w1,l1w2
constexpr size_t HB_W3T   = HB_W12T  + 4 * HS_W12T;
constexpr size_t HB_NORM  = HB_W3T   + 2 * HS_W3T;
constexpr size_t HB_XZC   = HB_NORM  + (size_t)BL * Dd;
constexpr size_t HB_DTBC  = HB_XZC   + (size_t)BL * XZC;
constexpr size_t HB_Y     = HB_DTBC  + 2 * (size_t)BL * DTBC;
constexpr size_t HB_MLPAB = HB_Y     + 2 * (size_t)BL * DI;
constexpr size_t TOTALH   = HB_MLPAB + (size_t)BL * Hh + 64;

constexpr float NEGF = -3.402823466e38f;

// Weight scale: weights ~N(0,0.02) sit in e4m3's subnormal range; scale up by
// 32 at conversion, undo with cscale=1/32 in every GEMM epilogue.
constexpr float WSC = 32.f;
constexpr float CSC = 1.f / 32.f;

// fp8 GEMM geometry: 128x128 tile, BK=64 fp8, 3-stage cp.async pipeline.
constexpr int GSTAGES = 3;
constexpr int SA8     = 80;               // bytes per smem row (64 data + 16 pad)
constexpr int TILE8   = 128 * SA8;        // 10240 B per operand per stage
constexpr int GSMEM8  = GSTAGES * 2 * TILE8;  // 61440 B dynamic
} // namespace

__device__ float g_buf[TOTALF];
__device__ __align__(16) unsigned char g_f8[TOTALH];
__device__ int   g_midx[BL];
__device__ int   g_mcount;

__device__ __forceinline__ float siluf(float x) { return x / (1.f + __expf(-x)); }

__device__ __forceinline__ uint32_t s2u(const void* p) {
  return (uint32_t)__cvta_generic_to_shared(p);
}

__device__ __forceinline__ void cp16s(uint32_t saddr, const void* gsrc, int szbytes) {
  asm volatile("cp.async.cg.shared.global [%0], [%1], 16, %2;\n"
               :: "r"(saddr), "l"(gsrc), "r"(szbytes));
}

__device__ __forceinline__ void ldsm4(unsigned& r0, unsigned& r1, unsigned& r2, unsigned& r3,
                                      const void* p) {
  unsigned a = s2u(p);
  asm volatile("ldmatrix.sync.aligned.m8n8.x4.shared.b16 {%0,%1,%2,%3}, [%4];\n"
               : "=r"(r0), "=r"(r1), "=r"(r2), "=r"(r3) : "r"(a));
}

__device__ __forceinline__ unsigned char f2f8(float x) {
  return (unsigned char)__nv_cvt_float_to_fp8(x, __NV_SATFINITE, __NV_E4M3);
}
__device__ __forceinline__ unsigned short f22f8(float a, float b) {
  float2 t = make_float2(a, b);
  return (unsigned short)__nv_cvt_float2_to_fp8x2(t, __NV_SATFINITE, __NV_E4M3);
}

// fp8 MMA: D[16x8] += A[16x32] * B[8x32]^T, fp32 accumulate
__device__ __forceinline__ void mma_fp8(float* c, const unsigned* a, const unsigned* b) {
  asm volatile(
      "mma.sync.aligned.m16n8k32.row.col.f32.e4m3.e4m3.f32 "
      "{%0,%1,%2,%3}, {%4,%5,%6,%7}, {%8,%9}, {%0,%1,%2,%3};\n"
      : "+f"(c[0]), "+f"(c[1]), "+f"(c[2]), "+f"(c[3])
      : "r"(a[0]), "r"(a[1]), "r"(a[2]), "r"(a[3]), "r"(b[0]), "r"(b[1]));
}

// ---------------------------------------------------------------------------
// Weight preprocessing -> fp8 (scaled by WSC)
// ---------------------------------------------------------------------------
__global__ void conv8_k(const float* __restrict__ in, unsigned char* __restrict__ out, int n) {
  int i = (blockIdx.x * blockDim.x + threadIdx.x) * 4;
  if (i + 3 >= n) {
    for (; i < n; i++) out[i] = f2f8(in[i] * WSC);
    return;
  }
  float4 v = *reinterpret_cast<const float4*>(in + i);
  unsigned lo = f22f8(v.x * WSC, v.y * WSC);
  unsigned hi = f22f8(v.z * WSC, v.w * WSC);
  *reinterpret_cast<unsigned*>(out + i) = lo | (hi << 16);
}

// out[n][k] = fp8(in[k][n] * WSC), batched over blockIdx.z
__global__ void tconv8_k(const float* __restrict__ in, unsigned char* __restrict__ out,
                         int K, int N, long instr, long outstr) {
  __shared__ float tile[32][33];
  in  += (size_t)blockIdx.z * instr;
  out += (size_t)blockIdx.z * outstr;
  int k0 = blockIdx.y * 32, n0 = blockIdx.x * 32;
  int x = threadIdx.x, y = threadIdx.y;
#pragma unroll
  for (int i = 0; i < 32; i += 8) {
    int k = k0 + y + i, n = n0 + x;
    tile[y + i][x] = (k < K && n < N) ? in[(size_t)k * N + n] : 0.f;
  }
  __syncthreads();
#pragma unroll
  for (int i = 0; i < 32; i += 8) {
    int n = n0 + y + i, k = k0 + x;
    if (n < N && k < K) out[(size_t)n * K + k] = f2f8(tile[x][y + i] * WSC);
  }
}

// ---------------------------------------------------------------------------
// Small kernels
// ---------------------------------------------------------------------------
__global__ void embed_k(const int* __restrict__ x_t, const float* __restrict__ tok,
                        const float* __restrict__ pos, float* __restrict__ h) {
  int row = blockIdx.x;
  int t   = x_t[row];
  int l   = row % Ll;
  const float* te = tok + (size_t)t * Dd;
  const float* pe = pos + (size_t)l * Dd;
  float* ho = h + (size_t)row * Dd;
  for (int d = threadIdx.x; d < Dd; d += blockDim.x) ho[d] = te[d] + pe[d];
}

__global__ void sigma_cond_k(const float* __restrict__ sigma,
                             const float* __restrict__ w1, const float* __restrict__ b1,
                             const float* __restrict__ w2, const float* __restrict__ b2,
                             float* __restrict__ c) {
  __shared__ float emb[FREQ];
  __shared__ float hid[CND];
  int b = blockIdx.x, i = threadIdx.x;
  float sg  = sigma[b];
  float f   = expf(-logf(10000.f) * (float)i / (float)(FREQ / 2));
  float arg = sg * f;
  emb[i]            = cosf(arg);
  emb[i + FREQ / 2] = sinf(arg);
  __syncthreads();
  float acc = b1[i];
  for (int j = 0; j < FREQ; j++) acc += emb[j] * w1[j * CND + i];
  hid[i] = siluf(acc);
  __syncthreads();
  float acc2 = b2[i];
  for (int j = 0; j < CND; j++) acc2 += hid[j] * w2[j * CND + i];
  c[b * CND + i] = acc2;
}

__global__ void adaln_cond_k(const float* __restrict__ c, const float* __restrict__ W,
                             const float* __restrict__ bias, float* __restrict__ cond) {
  int o = blockIdx.x * blockDim.x + threadIdx.x;
  if (o >= Bb * 3 * Dd) return;
  int b = o / (3 * Dd), col = o % (3 * Dd);
  float acc = bias[col];
  const float* cb = c + b * CND;
  for (int j = 0; j < CND; j++) acc += cb[j] * W[(size_t)j * 3 * Dd + col];
  cond[o] = acc;
}

__global__ void ln_mod_k(const float* __restrict__ h, const float* __restrict__ cond,
                         unsigned char* __restrict__ out) {
  __shared__ float red[256];
  int row = blockIdx.x, tid = threadIdx.x;
  int b = row / Ll;
  const float* x = h + (size_t)row * Dd;
  float v0 = x[tid], v1 = x[tid + 256], v2 = x[tid + 512];
  red[tid] = v0 + v1 + v2;
  __syncthreads();
  for (int s = 128; s > 0; s >>= 1) { if (tid < s) red[tid] += red[tid + s]; __syncthreads(); }
  float mu = red[0] / (float)Dd;
  __syncthreads();
  float d0 = v0 - mu, d1 = v1 - mu, d2 = v2 - mu;
  red[tid] = d0 * d0 + d1 * d1 + d2 * d2;
  __syncthreads();
  for (int s = 128; s > 0; s >>= 1) { if (tid < s) red[tid] += red[tid + s]; __syncthreads(); }
  float r = rsqrtf(red[0] / (float)Dd + 1e-5f);
  const float* shift = cond + (size_t)b * 3 * Dd;
  const float* scale = shift + Dd;
  unsigned char* o = out + (size_t)row * Dd;
  o[tid]       = f2f8(d0 * r * (1.f + scale[tid])       + shift[tid]);
  o[tid + 256] = f2f8(d1 * r * (1.f + scale[tid + 256]) + shift[tid + 256]);
  o[tid + 512] = f2f8(d2 * r * (1.f + scale[tid + 512]) + shift[tid + 512]);
}

// ---------------------------------------------------------------------------
// Pipelined fp8 tensor-core GEMM, batched over blockIdx.z.
// C[M,N] = (A[M,K] @ Bt[N,K]^T) * cscale.  128x128x64 tiles, 3-stage cp.async.
// ---------------------------------------------------------------------------
template <bool GATHER>
__global__ void __launch_bounds__(256, 2)
gemm_fp8_k(const unsigned char* __restrict__ A, int lda, long sA_,
           const unsigned char* __restrict__ Bt, int ldb, long sB_,
           float* __restrict__ C, int ldc, long sC_,
           unsigned char* __restrict__ C8,
           int M, int Nn, int K, float cscale,
           const int* __restrict__ midx, const int* __restrict__ mcount) {
  extern __shared__ __align__(128) unsigned char sm8[];
  unsigned char* As = sm8;
  unsigned char* Bs = sm8 + GSTAGES * TILE8;
  __shared__ int rowsm[128];

  int z = blockIdx.z;
  A  += (size_t)z * sA_;
  Bt += (size_t)z * sB_;
  if (C)  C  += (size_t)z * sC_;
  if (C8) C8 += (size_t)z * sC_;

  int tid = threadIdx.x;
  int m0 = blockIdx.y * 128, n0 = blockIdx.x * 128;
  if (GATHER) {
    M = *mcount;
    if (m0 >= M) return;
    if (tid < 128) rowsm[tid] = (m0 + tid < M) ? midx[m0 + tid] : -1;
    __syncthreads();
  }
  int warp = tid >> 5, lane = tid & 31;
  int wm = warp & 1, wn = warp >> 1;
  int gr = lane >> 2, tc = lane & 3;
  float acc[4][4][4] = {};

  // ldmatrix per-lane byte offsets (k32-fp8 fragments are byte-identical to
  // k16-bf16 ones; 80B row stride is bank-conflict-free: 5r mod 8 covers all)
  int arowb = (wm * 64 + (lane & 15)) * SA8 + (lane >> 4) * 16;
  int browb = (wn * 32 + (lane >> 4) * 8 + (lane & 7)) * SA8 + ((lane >> 3) & 1) * 16;

  int iters = (K + 63) / 64;

  auto load_stage = [&](int it, int s) {
    unsigned char* as = As + s * TILE8;
    unsigned char* bs = Bs + s * TILE8;
    int k0 = it * 64;
#pragma unroll
    for (int t = 0; t < 2; t++) {
      int idx = tid + t * 256;          // 512 16B chunks for A
      int r = idx >> 2, c = idx & 3;
      int gk = k0 + c * 16;
      int gm = GATHER ? rowsm[r] : (m0 + r);
      int ok = (gk < K && gm >= 0) ? 16 : 0;
      if (gm < 0) gm = 0;
      cp16s(s2u(as + r * SA8 + c * 16), A + (size_t)gm * lda + gk, ok);
    }
#pragma unroll
    for (int t = 0; t < 2; t++) {
      int idx = tid + t * 256;          // B chunks
      int r = idx >> 2, c = idx & 3;
      int gk = k0 + c * 16;
      int gn = n0 + r;
      int ok = (gk < K && gn < Nn) ? 16 : 0;
      if (gn >= Nn) gn = 0;
      cp16s(s2u(bs + r * SA8 + c * 16), Bt + (size_t)gn * ldb + gk, ok);
    }
  };

  load_stage(0, 0);
  asm volatile("cp.async.commit_group;\n");
  if (iters > 1) load_stage(1, 1);
  asm volatile("cp.async.commit_group;\n");

  for (int it = 0; it < iters; it++) {
    asm volatile("cp.async.wait_group 1;\n");
    __syncthreads();
    if (it + GSTAGES - 1 < iters) load_stage(it + GSTAGES - 1, (it + GSTAGES - 1) % GSTAGES);
    asm volatile("cp.async.commit_group;\n");

    int s = it % GSTAGES;
    const unsigned char* as = As + s * TILE8;
    const unsigned char* bs = Bs + s * TILE8;
#pragma unroll
    for (int ks = 0; ks < 2; ks++) {
      int kk = ks * 32;   // bytes (32 fp8 per k32 mma)
      unsigned ra[4][4], rb[4][2];
#pragma unroll
      for (int mi = 0; mi < 4; mi++)
        ldsm4(ra[mi][0], ra[mi][1], ra[mi][2], ra[mi][3],
              as + arowb + mi * 16 * SA8 + kk);
#pragma unroll
      for (int p = 0; p < 2; p++)
        ldsm4(rb[2 * p][0], rb[2 * p][1], rb[2 * p + 1][0], rb[2 * p + 1][1],
              bs + browb + p * 16 * SA8 + kk);
#pragma unroll
      for (int mi = 0; mi < 4; mi++)
#pragma unroll
        for (int ni = 0; ni < 4; ni++)
          mma_fp8(acc[mi][ni], ra[mi], rb[ni]);
    }
    __syncthreads();
  }

#pragma unroll
  for (int mi = 0; mi < 4; mi++) {
    int lr = wm * 64 + mi * 16 + gr;
    int gm0, gm1;
    if (GATHER) { gm0 = rowsm[lr]; gm1 = rowsm[lr + 8]; }
    else        { gm0 = m0 + lr;   gm1 = gm0 + 8; }
#pragma unroll
    for (int ni = 0; ni < 4; ni++) {
      int col = n0 + wn * 32 + ni * 8 + tc * 2;
      if (col >= Nn) continue;
      const float* cc = acc[mi][ni];
      float c0 = cc[0] * cscale, c1 = cc[1] * cscale;
      float c2 = cc[2] * cscale, c3 = cc[3] * cscale;
      if (gm0 >= 0) {
        if (C)  *reinterpret_cast<float2*>(C + (size_t)gm0 * ldc + col) = make_float2(c0, c1);
        if (C8) *reinterpret_cast<unsigned short*>(C8 + (size_t)gm0 * ldc + col) = f22f8(c0, c1);
      }
      if (gm1 >= 0) {
        if (C)  *reinterpret_cast<float2*>(C + (size_t)gm1 * ldc + col) = make_float2(c2, c3);
        if (C8) *reinterpret_cast<unsigned short*>(C8 + (size_t)gm1 * ldc + col) = f22f8(c2, c3);
      }
    }
  }
}

// ---------------------------------------------------------------------------
// Fused selective scan: softplus(delta+bias), scan, gate, fp8 out.
// ---------------------------------------------------------------------------
__global__ void scan_k(const float* __restrict__ delta_raw,  // [2][BL][DI]
                       const float* __restrict__ xzc,        // [BL][XZC]
                       const float* __restrict__ dtbc,       // [2][BL][DTBC]
                       const float* __restrict__ A_log,      // [2][DI][Ns]
                       const float* __restrict__ dt_bias,    // [2][DI]
                       const float* __restrict__ Dsk,        // [2][DI]
                       unsigned char* __restrict__ yb) {     // [2][BL][DI] fp8
  int tid = threadIdx.x;
  int nloc = tid & 15, dloc = tid >> 4;
  int d = blockIdx.x * 16 + dloc;
  int b = blockIdx.y;
  int dir = blockIdx.z;
  float a    = -expf(A_log[((size_t)dir * DI + d) * Ns + nloc]);
  float bias = dt_bias[dir * DI + d];
  float dskv = Dsk[dir * DI + d];
  const float* delp = delta_raw + (size_t)dir * BL * DI;
  const float* dtp  = dtbc + (size_t)dir * BL * DTBC;
  unsigned char* yp = yb + (size_t)dir * BL * DI;
  float hst = 0.f;
  for (int s = 0; s < Ll; s++) {
    int t = dir ? (Ll - 1 - s) : s;
    size_t row = (size_t)b * Ll + t;
    float dlr = delp[row * DI + d] + bias;
    float dl  = fmaxf(dlr, 0.f) + __logf(1.f + __expf(-fabsf(dlr)));
    float u   = xzc[row * XZC + dir * 2 * DI + d];
    float Bv  = dtp[row * DTBC + DTR + nloc];
    float Cv  = dtp[row * DTBC + DTR + Ns + nloc];
    hst = fmaf(__expf(dl * a), hst, dl * u * Bv);
    float ctr = hst * Cv;
    ctr += __shfl_down_sync(0xffffffffu, ctr, 8, 16);
    ctr += __shfl_down_sync(0xffffffffu, ctr, 4, 16);
    ctr += __shfl_down_sync(0xffffffffu, ctr, 2, 16);
    ctr += __shfl_down_sync(0xffffffffu, ctr, 1, 16);
    if (nloc == 0) {
      float zz = xzc[row * XZC + dir * 2 * DI + DI + d];
      yp[row * DI + d] = f2f8((ctr + u * dskv) * siluf(zz));
    }
  }
}

__global__ void combine_k(float* __restrict__ h, const float* __restrict__ cond,
                          const float* __restrict__ p0, const float* __restrict__ p1) {
  int i = blockIdx.x * blockDim.x + threadIdx.x;
  if (i >= BL * Dd) return;
  int d = i % Dd;
  int b = i / (Ll * Dd);
  float g = cond[(size_t)b * 3 * Dd + 2 * Dd + d];
  float v = p0[i];
  if (p1) v += p1[i];
  h[i] += g * v;
}

__global__ void silu_mul_k(const float* __restrict__ m12, unsigned char* __restrict__ out) {
  int i = blockIdx.x * blockDim.x + threadIdx.x;
  if (i >= BL * Hh) return;
  int row = i / Hh, hc = i % Hh;
  float av = m12[(size_t)row * 2 * Hh + hc];
  float bv = m12[(size_t)row * 2 * Hh + Hh + hc];
  out[i] = f2f8(siluf(av) * bv);
}

__global__ void build_mask_k(const int* __restrict__ x_t, int* __restrict__ midx,
                             int* __restrict__ mcount) {
  __shared__ int sf[BL];
  int i = threadIdx.x;
  int f = (x_t[i] == MASKID) ? 1 : 0;
  sf[i] = f;
  __syncthreads();
  for (int off = 1; off < BL; off <<= 1) {
    int v = (i >= off) ? sf[i - off] : 0;
    __syncthreads();
    sf[i] += v;
    __syncthreads();
  }
  if (f) midx[sf[i] - 1] = i;
  if (i == BL - 1) *mcount = sf[i];
}

__global__ void fill_forced_k(const int* __restrict__ x_t, float* __restrict__ out) {
  int row = blockIdx.x;
  int tok = x_t[row];
  if (tok == MASKID) return;
  float4* o = reinterpret_cast<float4*>(out + (size_t)row * Vv);
  for (int v4 = threadIdx.x; v4 < Vv / 4; v4 += blockDim.x) {
    int v = v4 * 4;
    float4 val = make_float4(NEGF, NEGF, NEGF, NEGF);
    if (tok >= v && tok < v + 4) (&val.x)[tok - v] = 0.f;
    o[v4] = val;
  }
}

__global__ void log_softmax_k(const int* __restrict__ x_t, float* __restrict__ out) {
  __shared__ float red[256];
  int row = blockIdx.x;
  if (x_t[row] != MASKID) return;
  float* o = out + (size_t)row * Vv;
  int tid = threadIdx.x;
  float m = NEGF;
  for (int v = tid; v < Vv; v += 256)
    if (v != MASKID) m = fmaxf(m, o[v]);
  red[tid] = m;
  __syncthreads();
  for (int s = 128; s > 0; s >>= 1) { if (tid < s) red[tid] = fmaxf(red[tid], red[tid + s]); __syncthreads(); }
  m = red[0];
  __syncthreads();
  float sum = 0.f;
  for (int v = tid; v < Vv; v += 256)
    if (v != MASKID) sum += __expf(o[v] - m);
  red[tid] = sum;
  __syncthreads();
  for (int s = 128; s > 0; s >>= 1) { if (tid < s) red[tid] += red[tid + s]; __syncthreads(); }
  float lse = m + logf(red[0]);
  __syncthreads();
  for (int v = tid; v < Vv; v += 256)
    o[v] = (v == MASKID) ? NEGF : (o[v] - lse);
}

// ---------------------------------------------------------------------------
// Host
// ---------------------------------------------------------------------------
static inline void run_gemm(const unsigned char* A, int lda, long sA,
                            const unsigned char* Bt, int ldb, long sB,
                            float* C, int ldc, long sC, unsigned char* C8,
                            int M, int N, int K, int nz) {
  dim3 g((N + 127) / 128, (M + 127) / 128, nz);
  gemm_fp8_k<false><<<g, 256, GSMEM8>>>(A, lda, sA, Bt, ldb, sB, C, ldc, sC, C8,
                                        M, N, K, CSC, nullptr, nullptr);
}

static inline void run_tconv(const float* in, unsigned char* out, int K, int N,
                             int nz, long instr, long outstr) {
  dim3 g((N + 31) / 32, (K + 31) / 32, nz);
  tconv8_k<<<g, dim3(32, 8)>>>(in, out, K, N, instr, outstr);
}

extern "C" void kernel_launch(void* const* d_in, const int* in_sizes, int n_in,
                              void* d_out, int out_size) {
  (void)in_sizes; (void)n_in; (void)out_size;
  const int*   x_t      = (const int*)  d_in[0];
  const float* sigma    = (const float*)d_in[1];
  const float* tok_emb  = (const float*)d_in[2];
  const float* pos_emb  = (const float*)d_in[3];
  const float* te_w1    = (const float*)d_in[4];
  const float* te_b1    = (const float*)d_in[5];
  const float* te_w2    = (const float*)d_in[6];
  const float* te_b2    = (const float*)d_in[7];
  const float* adaln1_w = (const float*)d_in[8];
  const float* adaln1_b = (const float*)d_in[9];
  const float* adaln2_w = (const float*)d_in[10];
  const float* adaln2_b = (const float*)d_in[11];
  const float* Win      = (const float*)d_in[12];
  const float* Wx       = (const float*)d_in[13];
  const float* Wdt      = (const float*)d_in[14];
  const float* dt_bias  = (const float*)d_in[15];
  const float* A_log    = (const float*)d_in[16];
  const float* Dskip    = (const float*)d_in[17];
  const float* Wout     = (const float*)d_in[18];
  const float* mlp_w1   = (const float*)d_in[19];
  const float* mlp_w2   = (const float*)d_in[20];
  const float* mlp_w3   = (const float*)d_in[21];
  const float* oad_w    = (const float*)d_in[22];
  const float* oad_b    = (const float*)d_in[23];
  float* out = (float*)d_out;

  cudaFuncSetAttribute(gemm_fp8_k<false>, cudaFuncAttributeMaxDynamicSharedMemorySize, GSMEM8);
  cudaFuncSetAttribute(gemm_fp8_k<true>,  cudaFuncAttributeMaxDynamicSharedMemorySize, GSMEM8);

  float* buf = nullptr;
  unsigned char* f8p = nullptr;
  int* midx = nullptr;
  int* mcount = nullptr;
  cudaGetSymbolAddress((void**)&buf, g_buf);
  cudaGetSymbolAddress((void**)&f8p, g_f8);
  cudaGetSymbolAddress((void**)&midx, g_midx);
  cudaGetSymbolAddress((void**)&mcount, g_mcount);

  float* h     = buf + OFF_H;
  float* c     = buf + OFF_C;
  float* cond  = buf + OFF_COND;
  float* xzc   = buf + OFF_XZC;
  float* dtbc  = buf + OFF_DTBC;
  float* delta = buf + OFF_DELTA;
  float* yo    = buf + OFF_YO;
  float* mlp12 = buf + OFF_MLP12;

  unsigned char* TE8    = f8p + HB_TE;
  unsigned char* normb  = f8p + HB_NORM;
  unsigned char* xzcb   = f8p + HB_XZC;
  unsigned char* dtbcb  = f8p + HB_DTBC;
  unsigned char* ybb    = f8p + HB_Y;
  unsigned char* mlpab  = f8p + HB_MLPAB;

  const int EW_D  = (BL * Dd + 255) / 256;
  const int EW_H  = (BL * Hh + 255) / 256;

  // ---- prefix ordered so launch index 5 (ncu -s 5 -c 1) is the Win GEMM ----
  run_tconv(Win, f8p + HB_WINT, Dd, 2 * DI, 4, (long)Dd * 2 * DI, (long)HS_WINT); // 1
  embed_k<<<BL, 256>>>(x_t, tok_emb, pos_emb, h);                                 // 2
  sigma_cond_k<<<Bb, 128>>>(sigma, te_w1, te_b1, te_w2, te_b2, c);                // 3
  adaln_cond_k<<<(Bb * 3 * Dd) / 256, 256>>>(c, adaln1_w, adaln1_b, cond);        // 4
  ln_mod_k<<<BL, 256>>>(h, cond, normb);                                          // 5
  run_gemm(normb, Dd, 0, f8p + HB_WINT, Dd, 0, xzc, XZC, 0, xzcb,                 // 6 <- profiled
           BL, XZC, Dd, 1);

  // ---- remaining preprocessing ----
  {
    int n = Vv * Dd;
    conv8_k<<<(n / 4 + 255) / 256, 256>>>(tok_emb, TE8, n);
  }
  run_tconv(Wx,   f8p + HB_WXT,   DI, DTBC,   4, (long)DI * DTBC,   (long)HS_WXT);
  run_tconv(Wdt,  f8p + HB_WDTT,  DTR, DI,    4, (long)DTR * DI,    (long)HS_WDTT);
  run_tconv(Wout, f8p + HB_WOUTT, DI, Dd,     4, (long)DI * Dd,     (long)HS_WOUTT);
  run_tconv(mlp_w1, f8p + HB_W12T,            Dd, Hh, 2, (long)Dd * Hh, 2 * (long)HS_W12T);
  run_tconv(mlp_w2, f8p + HB_W12T + HS_W12T,  Dd, Hh, 2, (long)Dd * Hh, 2 * (long)HS_W12T);
  run_tconv(mlp_w3, f8p + HB_W3T,             Hh, Dd, 2, (long)Hh * Dd, (long)HS_W3T);
  build_mask_k<<<1, BL>>>(x_t, midx, mcount);
  fill_forced_k<<<BL, 256>>>(x_t, out);

  for (int l = 0; l < NL; l++) {
    // ---- SSM block ----
    if (l > 0) {
      adaln_cond_k<<<(Bb * 3 * Dd) / 256, 256>>>(c, adaln1_w + (size_t)l * CND * 3 * Dd,
                                                 adaln1_b + (size_t)l * 3 * Dd, cond);
      ln_mod_k<<<BL, 256>>>(h, cond, normb);
      run_gemm(normb, Dd, 0, f8p + HB_WINT + (size_t)(2 * l) * HS_WINT, Dd, 0,
               xzc, XZC, 0, xzcb, BL, XZC, Dd, 1);
    }
    run_gemm(xzcb, XZC, (long)(2 * DI), f8p + HB_WXT + (size_t)(2 * l) * HS_WXT, DI, (long)HS_WXT,
             dtbc, DTBC, (long)BL * DTBC, dtbcb, BL, DTBC, DI, 2);
    run_gemm(dtbcb, DTBC, (long)BL * DTBC, f8p + HB_WDTT + (size_t)(2 * l) * HS_WDTT, DTR, (long)HS_WDTT,
             delta, DI, (long)BL * DI, nullptr, BL, DI, DTR, 2);
    scan_k<<<dim3(DI / 16, Bb, 2), 256>>>(delta, xzc, dtbc,
                                          A_log + (size_t)l * 2 * DI * Ns,
                                          dt_bias + (size_t)l * 2 * DI,
                                          Dskip + (size_t)l * 2 * DI, ybb);
    run_gemm(ybb, DI, (long)BL * DI, f8p + HB_WOUTT + (size_t)(2 * l) * HS_WOUTT, DI, (long)HS_WOUTT,
             yo, Dd, (long)BL * Dd, nullptr, BL, Dd, DI, 2);
    combine_k<<<EW_D, 256>>>(h, cond, yo, yo + (size_t)BL * Dd);

    // ---- MLP block ----
    adaln_cond_k<<<(Bb * 3 * Dd) / 256, 256>>>(c, adaln2_w + (size_t)l * CND * 3 * Dd,
                                               adaln2_b + (size_t)l * 3 * Dd, cond);
    ln_mod_k<<<BL, 256>>>(h, cond, normb);
    run_gemm(normb, Dd, 0, f8p + HB_W12T + (size_t)(2 * l) * HS_W12T, Dd, 0,
             mlp12, 2 * Hh, 0, nullptr, BL, 2 * Hh, Dd, 1);
    silu_mul_k<<<EW_H, 256>>>(mlp12, mlpab);
    run_gemm(mlpab, Hh, 0, f8p + HB_W3T + (size_t)l * HS_W3T, Hh, 0,
             yo, Dd, 0, nullptr, BL, Dd, Hh, 1);
    combine_k<<<EW_D, 256>>>(h, cond, yo, nullptr);
  }

  // ---- Output head ----
  adaln_cond_k<<<(Bb * 3 * Dd) / 256, 256>>>(c, oad_w, oad_b, cond);
  ln_mod_k<<<BL, 256>>>(h, cond, normb);
  {
    dim3 g((Vv + 127) / 128, BL / 128, 1);
    gemm_fp8_k<true><<<g, 256, GSMEM8>>>(normb, Dd, 0, TE8, Dd, 0, out, Vv, 0, nullptr,
                                         BL, Vv, Dd, CSC, midx, mcount);
  }
  log_softmax_k<<<BL, 256>>>(x_t, out);
}